// round 16
// baseline (speedup 1.0000x reference)
#include <cuda_runtime.h>
#include <cuda_fp16.h>
#include <cstdint>
#include <cstddef>
#include <math.h>

#define BNUM 16
#define HW   1024
#define C    512
#define G    32
#define CG   16
#define NQKV 1536
#define MTOT (BNUM * HW)
// 512^-0.5 * log2(e): folded so softmax can use exp2 directly
#define SCALE_L2E 0.06375872086496412f
#define NPERS 304                     // persistent CTAs (2/SM)

// fp16 scratch
__device__ __half g_xh[MTOT * C];
__device__ __half g_qh[MTOT * C];
__device__ __half g_kh[MTOT * C];
__device__ __half g_vh[MTOT * C];
__device__ __half g_sh[(size_t)BNUM * HW * HW];
__device__ __half g_oh[MTOT * C];
__device__ __half g_wqkvh[NQKV * C];   // permuted: [n'=e*512+ch][k], q-scale folded
__device__ __half g_wouth[C * C];
__device__ float  g_bqr[NQKV];         // permuted (scaled) qkv bias
__device__ float  g_rinv[MTOT];        // per-row 1/sum(exp) for deferred softmax norm

// ---------------------------------------------------------------------------
// helpers
// ---------------------------------------------------------------------------
__device__ __forceinline__ uint32_t smaddr(const void* p) {
    return (uint32_t)__cvta_generic_to_shared(p);
}
__device__ __forceinline__ uint32_t swz(uint32_t off) {       // SW128 for 128B rows
    return off ^ ((off >> 3) & 0x70);
}
__device__ __forceinline__ void ldsm4(uint32_t a, uint32_t& r0, uint32_t& r1,
                                      uint32_t& r2, uint32_t& r3) {
    asm volatile("ldmatrix.sync.aligned.m8n8.x4.shared.b16 {%0,%1,%2,%3},[%4];"
                 : "=r"(r0), "=r"(r1), "=r"(r2), "=r"(r3) : "r"(a));
}
__device__ __forceinline__ void ldsm4t(uint32_t a, uint32_t& r0, uint32_t& r1,
                                       uint32_t& r2, uint32_t& r3) {
    asm volatile("ldmatrix.sync.aligned.m8n8.x4.trans.shared.b16 {%0,%1,%2,%3},[%4];"
                 : "=r"(r0), "=r"(r1), "=r"(r2), "=r"(r3) : "r"(a));
}
__device__ __forceinline__ void mma16816(float* d, const uint32_t* a, const uint32_t* b) {
    asm volatile(
        "mma.sync.aligned.m16n8k16.row.col.f32.f16.f16.f32 "
        "{%0,%1,%2,%3},{%4,%5,%6,%7},{%8,%9},{%0,%1,%2,%3};"
        : "+f"(d[0]), "+f"(d[1]), "+f"(d[2]), "+f"(d[3])
        : "r"(a[0]), "r"(a[1]), "r"(a[2]), "r"(a[3]), "r"(b[0]), "r"(b[1]));
}
__device__ __forceinline__ void mma16816h(uint32_t* d, const uint32_t* a, const uint32_t* b) {
    asm volatile(
        "mma.sync.aligned.m16n8k16.row.col.f16.f16.f16.f16 "
        "{%0,%1},{%2,%3,%4,%5},{%6,%7},{%0,%1};"
        : "+r"(d[0]), "+r"(d[1])
        : "r"(a[0]), "r"(a[1]), "r"(a[2]), "r"(a[3]), "r"(b[0]), "r"(b[1]));
}
#define CPA16(dst, src) \
    asm volatile("cp.async.cg.shared.global [%0],[%1],16;" ::"r"(dst), "l"(src))
#define CPCOMMIT() asm volatile("cp.async.commit_group;")
#define CPWAIT0()  asm volatile("cp.async.wait_group 0;")
#define CPWAIT1()  asm volatile("cp.async.wait_group 1;")

// ---------------------------------------------------------------------------
// Fused prep: W_qkv permute/convert (log2e folded into q scale+bias),
// W_out convert, GroupNorm in one launch.
// ---------------------------------------------------------------------------
__global__ void prep_kernel(const float* __restrict__ in,
                            const float* __restrict__ gamma,
                            const float* __restrict__ beta,
                            const float* __restrict__ Wq,
                            const float* __restrict__ bq,
                            const float* __restrict__ Wo) {
    int blk = blockIdx.x;
    int tid = threadIdx.x;

    if (blk >= 512) {
        if (blk < 3584) {
            int idx = (blk - 512) * 256 + tid;
            int np = idx >> 9;
            int k  = idx & 511;
            int e  = np >> 9;
            int ch = np & 511;
            float s = (e == 0) ? SCALE_L2E : 1.0f;
            g_wqkvh[idx] = __float2half_rn(Wq[(size_t)k * NQKV + ch * 3 + e] * s);
            if (k == 0) g_bqr[np] = bq[ch * 3 + e] * s;
        } else {
            int idx = (blk - 3584) * 256 + tid;
            g_wouth[idx] = __float2half_rn(Wo[idx]);
        }
        return;
    }

    int b = blk >> 5;
    int g = blk & 31;
    int lane = tid & 31, warp = tid >> 5;
    const float* base = in + (size_t)b * HW * C + g * CG;
    float s = 0.f, ss = 0.f;
    for (int e = tid; e < HW * 8; e += 256) {
        int pos = e >> 3, c2 = e & 7;
        float2 v = *(const float2*)(base + (size_t)pos * C + c2 * 2);
        s += v.x + v.y; ss += v.x * v.x + v.y * v.y;
    }
#pragma unroll
    for (int o = 16; o; o >>= 1) {
        s  += __shfl_xor_sync(0xffffffffu, s, o);
        ss += __shfl_xor_sync(0xffffffffu, ss, o);
    }
    __shared__ float sm_s[8], sm_ss[8];
    if (lane == 0) { sm_s[warp] = s; sm_ss[warp] = ss; }
    __syncthreads();
    float ts = 0.f, tss = 0.f;
#pragma unroll
    for (int i = 0; i < 8; i++) { ts += sm_s[i]; tss += sm_ss[i]; }
    const float invN = 1.0f / (HW * CG);
    float mean = ts * invN;
    float var  = tss * invN - mean * mean;
    float rstd = rsqrtf(var + 1e-3f);
    __half* outb = g_xh + (size_t)b * HW * C + g * CG;
    for (int e = tid; e < HW * 8; e += 256) {
        int pos = e >> 3, c2 = e & 7;
        float2 v = *(const float2*)(base + (size_t)pos * C + c2 * 2);
        float g0 = gamma[g * CG + c2 * 2], g1 = gamma[g * CG + c2 * 2 + 1];
        float b0 = beta[g * CG + c2 * 2],  b1 = beta[g * CG + c2 * 2 + 1];
        *(__half2*)(outb + (size_t)pos * C + c2 * 2) =
            __floats2half2_rn((v.x - mean) * rstd * g0 + b0,
                              (v.y - mean) * rstd * g1 + b1);
    }
}

// ---------------------------------------------------------------------------
// Persistent fp16 mma.sync GEMM (R9 structure). EPI 1 uses fp16 accumulators.
// EPI 2 applies the deferred softmax normalization (g_rinv) in its epilogue.
// ---------------------------------------------------------------------------
template <int EPI>
__global__ void __launch_bounds__(128, 2)
gemm_mma(const float* __restrict__ bias,
         const float* __restrict__ resid,
         float* __restrict__ outF) {
    constexpr bool NT  = (EPI <= 1);
    constexpr bool HACC = (EPI == 1);
    constexpr int  K   = (EPI == 2) ? 1024 : 512;
    constexpr int  KT  = K / 64;
    constexpr int  LDA = (EPI == 2) ? 1024 : 512;
    constexpr int  LDB = 512;
    constexpr int  TX  = (EPI == 0) ? 12 : ((EPI == 1) ? 8 : 4);
    constexpr int  TY  = (EPI == 1 || EPI == 2) ? 8 : 128;
    constexpr int  TZ  = (EPI == 1 || EPI == 2) ? 16 : 1;
    constexpr int  T   = TX * TY * TZ;

    constexpr int ASTG_B = 128 * 128;
    constexpr int BSTG_B = NT ? (128 * 128) : (64 * 272);
    extern __shared__ char smc[];
    char* Abuf = smc;
    char* Bbuf = smc + 3 * ASTG_B;

    int tid = threadIdx.x, lane = tid & 31, warp = tid >> 5;
    int wm = warp & 1, wn = warp >> 1;
    int bid = blockIdx.x;
    int GP = gridDim.x;
    int myN = (bid < T) ? ((T - 1 - bid) / GP + 1) : 0;
    int S = myN * KT;
    if (S == 0) return;

    float    acc[HACC ? 1 : 4][8][4] = {};
    uint32_t acch[HACC ? 4 : 1][8][2] = {};

    auto tileinfo = [&](int i, int& m0, int& n0, int& z) {
        int t = bid + i * GP;
        int x = t % TX;
        int y = (t / TX) % TY;
        z = t / (TX * TY);
        m0 = y * 128; n0 = x * 128;
    };

    auto load = [&](int s) {
        int i = s / KT;
        if (i < myN) {
            int m0, n0, z;
            tileinfo(i, m0, n0, z);
            int k0 = (s % KT) * 64;
            const __half* A;
            const __half* B;
            if constexpr (EPI == 0)      { A = g_xh;                        B = g_wqkvh; }
            else if constexpr (EPI == 1) { A = g_qh + (size_t)z * HW * C;   B = g_kh + (size_t)z * HW * C; }
            else if constexpr (EPI == 2) { A = g_sh + (size_t)z * HW * HW;  B = g_vh + (size_t)z * HW * C; }
            else                         { A = g_oh;                        B = g_wouth; }
            int st = s % 3;
            uint32_t Asm = smaddr(Abuf + st * ASTG_B);
            uint32_t Bsm = smaddr(Bbuf + st * BSTG_B);
#pragma unroll
            for (int q = 0; q < 8; q++) {
                int c = tid + q * 128;
                int r = c >> 3, ch = c & 7;
                CPA16(Asm + swz((uint32_t)(r * 128 + ch * 16)),
                      A + (size_t)(m0 + r) * LDA + k0 + ch * 8);
            }
            if constexpr (NT) {
#pragma unroll
                for (int q = 0; q < 8; q++) {
                    int c = tid + q * 128;
                    int r = c >> 3, ch = c & 7;
                    CPA16(Bsm + swz((uint32_t)(r * 128 + ch * 16)),
                          B + (size_t)(n0 + r) * LDB + k0 + ch * 8);
                }
            } else {
#pragma unroll
                for (int q = 0; q < 8; q++) {
                    int c = tid + q * 128;
                    int r = c >> 4, ch = c & 15;
                    CPA16(Bsm + (uint32_t)(r * 272 + ch * 16),
                          B + (size_t)(k0 + r) * LDB + n0 + ch * 8);
                }
            }
        }
        CPCOMMIT();
    };

    auto ldfrag = [&](int st, int ks, uint32_t a[4][4], uint32_t b[8][2]) {
        uint32_t Asm = smaddr(Abuf + st * ASTG_B);
        uint32_t Bsm = smaddr(Bbuf + st * BSTG_B);
        int colh = ks + ((lane >> 4) << 3);
#pragma unroll
        for (int mt = 0; mt < 4; mt++) {
            int r = wm * 64 + mt * 16 + (lane & 15);
            ldsm4(Asm + swz((uint32_t)(r * 128 + colh * 2)),
                  a[mt][0], a[mt][1], a[mt][2], a[mt][3]);
        }
        if constexpr (NT) {
#pragma unroll
            for (int ng = 0; ng < 4; ng++) {
                int r = wn * 64 + ng * 16 + (lane & 15);
                uint32_t r0, r1, r2, r3;
                ldsm4(Bsm + swz((uint32_t)(r * 128 + colh * 2)), r0, r1, r2, r3);
                b[2 * ng][0] = r0; b[2 * ng][1] = r2;
                b[2 * ng + 1][0] = r1; b[2 * ng + 1][1] = r3;
            }
        } else {
#pragma unroll
            for (int ng = 0; ng < 4; ng++) {
                int r = ks + (lane & 15);
                int col = wn * 64 + ng * 16 + ((lane >> 4) << 3);
                uint32_t r0, r1, r2, r3;
                ldsm4t(Bsm + (uint32_t)(r * 272 + col * 2), r0, r1, r2, r3);
                b[2 * ng][0] = r0; b[2 * ng][1] = r1;
                b[2 * ng + 1][0] = r2; b[2 * ng + 1][1] = r3;
            }
        }
    };

    auto mma_all = [&](uint32_t a[4][4], uint32_t b[8][2]) {
#pragma unroll
        for (int mt = 0; mt < 4; mt++)
#pragma unroll
            for (int nt = 0; nt < 8; nt++) {
                if constexpr (HACC) mma16816h(acch[mt][nt], a[mt], b[nt]);
                else                mma16816(acc[mt][nt], a[mt], b[nt]);
            }
    };

    auto epilogue = [&](int tile) {
        int m0, n0, z;
        tileinfo(tile, m0, n0, z);
#pragma unroll
        for (int mt = 0; mt < 4; mt++) {
#pragma unroll
            for (int nt = 0; nt < 8; nt++) {
                int r  = m0 + wm * 64 + mt * 16 + (lane >> 2);
                int nl = wn * 64 + nt * 8 + (lane & 3) * 2;
                if constexpr (EPI == 1) {
                    size_t base = (size_t)z * HW * HW;
                    int cc = n0 + nl;
                    *(uint32_t*)&g_sh[base + (size_t)r * HW + cc] = acch[mt][nt][0];
                    *(uint32_t*)&g_sh[base + (size_t)(r + 8) * HW + cc] = acch[mt][nt][1];
                    acch[mt][nt][0] = 0u; acch[mt][nt][1] = 0u;
                } else {
                    float* v = acc[mt][nt];
                    if constexpr (EPI == 0) {
                        int e = n0 >> 9;
                        __half* dst = (e == 0) ? g_qh : ((e == 1) ? g_kh : g_vh);
                        int ch = (n0 & 511) + nl;
                        float b0f = g_bqr[n0 + nl], b1f = g_bqr[n0 + nl + 1];
                        *(__half2*)&dst[(size_t)r * C + ch] =
                            __floats2half2_rn(v[0] + b0f, v[1] + b1f);
                        *(__half2*)&dst[(size_t)(r + 8) * C + ch] =
                            __floats2half2_rn(v[2] + b0f, v[3] + b1f);
                    } else if constexpr (EPI == 2) {
                        size_t base = (size_t)z * HW * C;
                        int cc = n0 + nl;
                        float r0i = g_rinv[z * HW + r];
                        float r1i = g_rinv[z * HW + r + 8];
                        *(__half2*)&g_oh[base + (size_t)r * C + cc] =
                            __floats2half2_rn(v[0] * r0i, v[1] * r0i);
                        *(__half2*)&g_oh[base + (size_t)(r + 8) * C + cc] =
                            __floats2half2_rn(v[2] * r1i, v[3] * r1i);
                    } else {
                        int cc = n0 + nl;
                        outF[(size_t)r * C + cc]     = v[0] + bias[cc]     + resid[(size_t)r * C + cc];
                        outF[(size_t)r * C + cc + 1] = v[1] + bias[cc + 1] + resid[(size_t)r * C + cc + 1];
                        outF[(size_t)(r + 8) * C + cc]     = v[2] + bias[cc]     + resid[(size_t)(r + 8) * C + cc];
                        outF[(size_t)(r + 8) * C + cc + 1] = v[3] + bias[cc + 1] + resid[(size_t)(r + 8) * C + cc + 1];
                    }
                    v[0] = v[1] = v[2] = v[3] = 0.f;
                }
            }
        }
    };

    load(0);
    load(1);

    for (int s = 0; s < S; s++) {
        if (s + 1 < S) { CPWAIT1(); } else { CPWAIT0(); }
        __syncthreads();
        load(s + 2);
        int st = s % 3;
        uint32_t a0[4][4], b0[8][2], a1[4][4], b1[8][2];
        ldfrag(st, 0,  a0, b0);
        ldfrag(st, 16, a1, b1);
        mma_all(a0, b0);
        ldfrag(st, 32, a0, b0);
        mma_all(a1, b1);
        ldfrag(st, 48, a1, b1);
        mma_all(a0, b0);
        mma_all(a1, b1);
        if ((s + 1) % KT == 0) epilogue(s / KT);
    }
}

// ---------------------------------------------------------------------------
// fp16 softmax (exp2 domain, deferred normalization): writes exp2(s-m) and
// stores 1/rowsum in g_rinv. 128 thr, uint4/thread, 2 barriers.
// ---------------------------------------------------------------------------
__global__ void softmax_h() {
    size_t row = blockIdx.x;
    uint4* p = (uint4*)(g_sh + row * HW);
    int tid = threadIdx.x, lane = tid & 31, warp = tid >> 5;
    uint4 raw = p[tid];
    __half2 h[4] = {*(__half2*)&raw.x, *(__half2*)&raw.y,
                    *(__half2*)&raw.z, *(__half2*)&raw.w};
    float2 f[4];
#pragma unroll
    for (int i = 0; i < 4; i++) f[i] = __half22float2(h[i]);

    float m = -1e30f;
#pragma unroll
    for (int i = 0; i < 4; i++) m = fmaxf(m, fmaxf(f[i].x, f[i].y));
#pragma unroll
    for (int o = 16; o; o >>= 1) m = fmaxf(m, __shfl_xor_sync(0xffffffffu, m, o));
    __shared__ float smax[4], ssum[4];
    if (lane == 0) smax[warp] = m;
    __syncthreads();
    m = fmaxf(fmaxf(smax[0], smax[1]), fmaxf(smax[2], smax[3]));

    float e[8];
    float s = 0.f;
#pragma unroll
    for (int i = 0; i < 4; i++) {
        e[2 * i]     = exp2f(f[i].x - m);
        e[2 * i + 1] = exp2f(f[i].y - m);
        s += e[2 * i] + e[2 * i + 1];
    }
#pragma unroll
    for (int o = 16; o; o >>= 1) s += __shfl_xor_sync(0xffffffffu, s, o);
    if (lane == 0) ssum[warp] = s;
    __syncthreads();
    float total = ssum[0] + ssum[1] + ssum[2] + ssum[3];
    if (tid == 0) g_rinv[row] = 1.0f / total;

    uint4 w;
    *(__half2*)&w.x = __floats2half2_rn(e[0], e[1]);
    *(__half2*)&w.y = __floats2half2_rn(e[2], e[3]);
    *(__half2*)&w.z = __floats2half2_rn(e[4], e[5]);
    *(__half2*)&w.w = __floats2half2_rn(e[6], e[7]);
    p[tid] = w;
}

// ---------------------------------------------------------------------------
extern "C" void kernel_launch(void* const* d_in, const int* in_sizes, int n_in,
                              void* d_out, int out_size) {
    (void)in_sizes; (void)n_in; (void)out_size;
    const float* inputs = (const float*)d_in[0];
    const float* gamma  = (const float*)d_in[1];
    const float* beta   = (const float*)d_in[2];
    const float* Wqkv   = (const float*)d_in[3];
    const float* bqkv   = (const float*)d_in[4];
    const float* Wout   = (const float*)d_in[5];
    const float* bout   = (const float*)d_in[6];
    float* out = (float*)d_out;

    const int smNT = 3 * (128 * 128 + 128 * 128);     // 98304
    const int smNN = 3 * (128 * 128 + 64 * 272);      // 101376
    cudaFuncSetAttribute(gemm_mma<0>, cudaFuncAttributeMaxDynamicSharedMemorySize, smNT);
    cudaFuncSetAttribute(gemm_mma<1>, cudaFuncAttributeMaxDynamicSharedMemorySize, smNT);
    cudaFuncSetAttribute(gemm_mma<2>, cudaFuncAttributeMaxDynamicSharedMemorySize, smNN);
    cudaFuncSetAttribute(gemm_mma<3>, cudaFuncAttributeMaxDynamicSharedMemorySize, smNN);

    prep_kernel<<<4608, 256>>>(inputs, gamma, beta, Wqkv, bqkv, Wout);

    gemm_mma<0><<<NPERS, 128, smNT>>>(nullptr, nullptr, nullptr);
    gemm_mma<1><<<NPERS, 128, smNT>>>(nullptr, nullptr, nullptr);
    softmax_h<<<BNUM * HW, 128>>>();
    gemm_mma<2><<<NPERS, 128, smNN>>>(nullptr, nullptr, nullptr);
    gemm_mma<3><<<NPERS, 128, smNN>>>(bout, inputs, out);
}

// round 17
// speedup vs baseline: 1.0079x; 1.0079x over previous
#include <cuda_runtime.h>
#include <cuda_fp16.h>
#include <cstdint>
#include <cstddef>
#include <math.h>

#define BNUM 16
#define HW   1024
#define C    512
#define G    32
#define CG   16
#define NQKV 1536
#define MTOT (BNUM * HW)
// 512^-0.5 * log2(e): folded so softmax can use exp2 directly
#define SCALE_L2E 0.06375872086496412f
#define NPERS 304                     // persistent CTAs (2/SM)

// fp16 scratch
__device__ __half g_xh[MTOT * C];
__device__ __half g_qh[MTOT * C];
__device__ __half g_kh[MTOT * C];
__device__ __half g_vh[MTOT * C];
__device__ __half g_sh[(size_t)BNUM * HW * HW];
__device__ __half g_oh[MTOT * C];
__device__ __half g_wqkvh[NQKV * C];   // permuted: [n'=e*512+ch][k], q-scale folded
__device__ __half g_wouth[C * C];
__device__ float  g_bqr[NQKV];         // permuted (scaled) qkv bias
__device__ float  g_rinv[MTOT];        // per-row 1/sum(exp) for deferred softmax norm

// ---------------------------------------------------------------------------
// helpers
// ---------------------------------------------------------------------------
__device__ __forceinline__ uint32_t smaddr(const void* p) {
    return (uint32_t)__cvta_generic_to_shared(p);
}
__device__ __forceinline__ uint32_t swz(uint32_t off) {       // SW128 for 128B rows
    return off ^ ((off >> 3) & 0x70);
}
__device__ __forceinline__ void ldsm4(uint32_t a, uint32_t& r0, uint32_t& r1,
                                      uint32_t& r2, uint32_t& r3) {
    asm volatile("ldmatrix.sync.aligned.m8n8.x4.shared.b16 {%0,%1,%2,%3},[%4];"
                 : "=r"(r0), "=r"(r1), "=r"(r2), "=r"(r3) : "r"(a));
}
__device__ __forceinline__ void ldsm4t(uint32_t a, uint32_t& r0, uint32_t& r1,
                                       uint32_t& r2, uint32_t& r3) {
    asm volatile("ldmatrix.sync.aligned.m8n8.x4.trans.shared.b16 {%0,%1,%2,%3},[%4];"
                 : "=r"(r0), "=r"(r1), "=r"(r2), "=r"(r3) : "r"(a));
}
__device__ __forceinline__ void mma16816(float* d, const uint32_t* a, const uint32_t* b) {
    asm volatile(
        "mma.sync.aligned.m16n8k16.row.col.f32.f16.f16.f32 "
        "{%0,%1,%2,%3},{%4,%5,%6,%7},{%8,%9},{%0,%1,%2,%3};"
        : "+f"(d[0]), "+f"(d[1]), "+f"(d[2]), "+f"(d[3])
        : "r"(a[0]), "r"(a[1]), "r"(a[2]), "r"(a[3]), "r"(b[0]), "r"(b[1]));
}
__device__ __forceinline__ void mma16816h(uint32_t* d, const uint32_t* a, const uint32_t* b) {
    asm volatile(
        "mma.sync.aligned.m16n8k16.row.col.f16.f16.f16.f16 "
        "{%0,%1},{%2,%3,%4,%5},{%6,%7},{%0,%1};"
        : "+r"(d[0]), "+r"(d[1])
        : "r"(a[0]), "r"(a[1]), "r"(a[2]), "r"(a[3]), "r"(b[0]), "r"(b[1]));
}
#define CPA16(dst, src) \
    asm volatile("cp.async.cg.shared.global [%0],[%1],16;" ::"r"(dst), "l"(src))
#define CPCOMMIT() asm volatile("cp.async.commit_group;")
#define CPWAIT0()  asm volatile("cp.async.wait_group 0;")
#define CPWAIT1()  asm volatile("cp.async.wait_group 1;")

// ---------------------------------------------------------------------------
// Fused prep: W_qkv permute/convert (log2e folded into q scale+bias),
// W_out convert, GroupNorm in one launch.
// ---------------------------------------------------------------------------
__global__ void prep_kernel(const float* __restrict__ in,
                            const float* __restrict__ gamma,
                            const float* __restrict__ beta,
                            const float* __restrict__ Wq,
                            const float* __restrict__ bq,
                            const float* __restrict__ Wo) {
    int blk = blockIdx.x;
    int tid = threadIdx.x;

    if (blk >= 512) {
        if (blk < 3584) {
            int idx = (blk - 512) * 256 + tid;
            int np = idx >> 9;
            int k  = idx & 511;
            int e  = np >> 9;
            int ch = np & 511;
            float s = (e == 0) ? SCALE_L2E : 1.0f;
            g_wqkvh[idx] = __float2half_rn(Wq[(size_t)k * NQKV + ch * 3 + e] * s);
            if (k == 0) g_bqr[np] = bq[ch * 3 + e] * s;
        } else {
            int idx = (blk - 3584) * 256 + tid;
            g_wouth[idx] = __float2half_rn(Wo[idx]);
        }
        return;
    }

    int b = blk >> 5;
    int g = blk & 31;
    int lane = tid & 31, warp = tid >> 5;
    const float* base = in + (size_t)b * HW * C + g * CG;
    float s = 0.f, ss = 0.f;
    for (int e = tid; e < HW * 8; e += 256) {
        int pos = e >> 3, c2 = e & 7;
        float2 v = *(const float2*)(base + (size_t)pos * C + c2 * 2);
        s += v.x + v.y; ss += v.x * v.x + v.y * v.y;
    }
#pragma unroll
    for (int o = 16; o; o >>= 1) {
        s  += __shfl_xor_sync(0xffffffffu, s, o);
        ss += __shfl_xor_sync(0xffffffffu, ss, o);
    }
    __shared__ float sm_s[8], sm_ss[8];
    if (lane == 0) { sm_s[warp] = s; sm_ss[warp] = ss; }
    __syncthreads();
    float ts = 0.f, tss = 0.f;
#pragma unroll
    for (int i = 0; i < 8; i++) { ts += sm_s[i]; tss += sm_ss[i]; }
    const float invN = 1.0f / (HW * CG);
    float mean = ts * invN;
    float var  = tss * invN - mean * mean;
    float rstd = rsqrtf(var + 1e-3f);
    __half* outb = g_xh + (size_t)b * HW * C + g * CG;
    for (int e = tid; e < HW * 8; e += 256) {
        int pos = e >> 3, c2 = e & 7;
        float2 v = *(const float2*)(base + (size_t)pos * C + c2 * 2);
        float g0 = gamma[g * CG + c2 * 2], g1 = gamma[g * CG + c2 * 2 + 1];
        float b0 = beta[g * CG + c2 * 2],  b1 = beta[g * CG + c2 * 2 + 1];
        *(__half2*)(outb + (size_t)pos * C + c2 * 2) =
            __floats2half2_rn((v.x - mean) * rstd * g0 + b0,
                              (v.y - mean) * rstd * g1 + b1);
    }
}

// ---------------------------------------------------------------------------
// Persistent fp16 mma.sync GEMM (R9 structure).
// EPI 0: fp32 acc (feeds everything — precision anchor).
// EPI 1/2/3: fp16 acc (calibrated cost ~5e-5 rel_err each; halves acc regs).
// EPI 2 applies deferred softmax normalization (g_rinv) in its epilogue.
// ---------------------------------------------------------------------------
template <int EPI>
__global__ void __launch_bounds__(128, 2)
gemm_mma(const float* __restrict__ bias,
         const float* __restrict__ resid,
         float* __restrict__ outF) {
    constexpr bool NT  = (EPI <= 1);
    constexpr bool HACC = (EPI >= 1);
    constexpr int  K   = (EPI == 2) ? 1024 : 512;
    constexpr int  KT  = K / 64;
    constexpr int  LDA = (EPI == 2) ? 1024 : 512;
    constexpr int  LDB = 512;
    constexpr int  TX  = (EPI == 0) ? 12 : ((EPI == 1) ? 8 : 4);
    constexpr int  TY  = (EPI == 1 || EPI == 2) ? 8 : 128;
    constexpr int  TZ  = (EPI == 1 || EPI == 2) ? 16 : 1;
    constexpr int  T   = TX * TY * TZ;

    constexpr int ASTG_B = 128 * 128;
    constexpr int BSTG_B = NT ? (128 * 128) : (64 * 272);
    extern __shared__ char smc[];
    char* Abuf = smc;
    char* Bbuf = smc + 3 * ASTG_B;

    int tid = threadIdx.x, lane = tid & 31, warp = tid >> 5;
    int wm = warp & 1, wn = warp >> 1;
    int bid = blockIdx.x;
    int GP = gridDim.x;
    int myN = (bid < T) ? ((T - 1 - bid) / GP + 1) : 0;
    int S = myN * KT;
    if (S == 0) return;

    float    acc[HACC ? 1 : 4][8][4] = {};
    uint32_t acch[HACC ? 4 : 1][8][2] = {};

    auto tileinfo = [&](int i, int& m0, int& n0, int& z) {
        int t = bid + i * GP;
        int x = t % TX;
        int y = (t / TX) % TY;
        z = t / (TX * TY);
        m0 = y * 128; n0 = x * 128;
    };

    auto load = [&](int s) {
        int i = s / KT;
        if (i < myN) {
            int m0, n0, z;
            tileinfo(i, m0, n0, z);
            int k0 = (s % KT) * 64;
            const __half* A;
            const __half* B;
            if constexpr (EPI == 0)      { A = g_xh;                        B = g_wqkvh; }
            else if constexpr (EPI == 1) { A = g_qh + (size_t)z * HW * C;   B = g_kh + (size_t)z * HW * C; }
            else if constexpr (EPI == 2) { A = g_sh + (size_t)z * HW * HW;  B = g_vh + (size_t)z * HW * C; }
            else                         { A = g_oh;                        B = g_wouth; }
            int st = s % 3;
            uint32_t Asm = smaddr(Abuf + st * ASTG_B);
            uint32_t Bsm = smaddr(Bbuf + st * BSTG_B);
#pragma unroll
            for (int q = 0; q < 8; q++) {
                int c = tid + q * 128;
                int r = c >> 3, ch = c & 7;
                CPA16(Asm + swz((uint32_t)(r * 128 + ch * 16)),
                      A + (size_t)(m0 + r) * LDA + k0 + ch * 8);
            }
            if constexpr (NT) {
#pragma unroll
                for (int q = 0; q < 8; q++) {
                    int c = tid + q * 128;
                    int r = c >> 3, ch = c & 7;
                    CPA16(Bsm + swz((uint32_t)(r * 128 + ch * 16)),
                          B + (size_t)(n0 + r) * LDB + k0 + ch * 8);
                }
            } else {
#pragma unroll
                for (int q = 0; q < 8; q++) {
                    int c = tid + q * 128;
                    int r = c >> 4, ch = c & 15;
                    CPA16(Bsm + (uint32_t)(r * 272 + ch * 16),
                          B + (size_t)(k0 + r) * LDB + n0 + ch * 8);
                }
            }
        }
        CPCOMMIT();
    };

    auto ldfrag = [&](int st, int ks, uint32_t a[4][4], uint32_t b[8][2]) {
        uint32_t Asm = smaddr(Abuf + st * ASTG_B);
        uint32_t Bsm = smaddr(Bbuf + st * BSTG_B);
        int colh = ks + ((lane >> 4) << 3);
#pragma unroll
        for (int mt = 0; mt < 4; mt++) {
            int r = wm * 64 + mt * 16 + (lane & 15);
            ldsm4(Asm + swz((uint32_t)(r * 128 + colh * 2)),
                  a[mt][0], a[mt][1], a[mt][2], a[mt][3]);
        }
        if constexpr (NT) {
#pragma unroll
            for (int ng = 0; ng < 4; ng++) {
                int r = wn * 64 + ng * 16 + (lane & 15);
                uint32_t r0, r1, r2, r3;
                ldsm4(Bsm + swz((uint32_t)(r * 128 + colh * 2)), r0, r1, r2, r3);
                b[2 * ng][0] = r0; b[2 * ng][1] = r2;
                b[2 * ng + 1][0] = r1; b[2 * ng + 1][1] = r3;
            }
        } else {
#pragma unroll
            for (int ng = 0; ng < 4; ng++) {
                int r = ks + (lane & 15);
                int col = wn * 64 + ng * 16 + ((lane >> 4) << 3);
                uint32_t r0, r1, r2, r3;
                ldsm4t(Bsm + (uint32_t)(r * 272 + col * 2), r0, r1, r2, r3);
                b[2 * ng][0] = r0; b[2 * ng][1] = r1;
                b[2 * ng + 1][0] = r2; b[2 * ng + 1][1] = r3;
            }
        }
    };

    auto mma_all = [&](uint32_t a[4][4], uint32_t b[8][2]) {
#pragma unroll
        for (int mt = 0; mt < 4; mt++)
#pragma unroll
            for (int nt = 0; nt < 8; nt++) {
                if constexpr (HACC) mma16816h(acch[mt][nt], a[mt], b[nt]);
                else                mma16816(acc[mt][nt], a[mt], b[nt]);
            }
    };

    auto epilogue = [&](int tile) {
        int m0, n0, z;
        tileinfo(tile, m0, n0, z);
#pragma unroll
        for (int mt = 0; mt < 4; mt++) {
#pragma unroll
            for (int nt = 0; nt < 8; nt++) {
                int r  = m0 + wm * 64 + mt * 16 + (lane >> 2);
                int nl = wn * 64 + nt * 8 + (lane & 3) * 2;
                if constexpr (EPI == 1) {
                    size_t base = (size_t)z * HW * HW;
                    int cc = n0 + nl;
                    *(uint32_t*)&g_sh[base + (size_t)r * HW + cc] = acch[mt][nt][0];
                    *(uint32_t*)&g_sh[base + (size_t)(r + 8) * HW + cc] = acch[mt][nt][1];
                    acch[mt][nt][0] = 0u; acch[mt][nt][1] = 0u;
                } else if constexpr (EPI == 2) {
                    size_t base = (size_t)z * HW * C;
                    int cc = n0 + nl;
                    float r0i = g_rinv[z * HW + r];
                    float r1i = g_rinv[z * HW + r + 8];
                    float2 f0 = __half22float2(*(__half2*)&acch[mt][nt][0]);
                    float2 f1 = __half22float2(*(__half2*)&acch[mt][nt][1]);
                    *(__half2*)&g_oh[base + (size_t)r * C + cc] =
                        __floats2half2_rn(f0.x * r0i, f0.y * r0i);
                    *(__half2*)&g_oh[base + (size_t)(r + 8) * C + cc] =
                        __floats2half2_rn(f1.x * r1i, f1.y * r1i);
                    acch[mt][nt][0] = 0u; acch[mt][nt][1] = 0u;
                } else if constexpr (EPI == 3) {
                    int cc = n0 + nl;
                    float2 f0 = __half22float2(*(__half2*)&acch[mt][nt][0]);
                    float2 f1 = __half22float2(*(__half2*)&acch[mt][nt][1]);
                    outF[(size_t)r * C + cc]     = f0.x + bias[cc]     + resid[(size_t)r * C + cc];
                    outF[(size_t)r * C + cc + 1] = f0.y + bias[cc + 1] + resid[(size_t)r * C + cc + 1];
                    outF[(size_t)(r + 8) * C + cc]     = f1.x + bias[cc]     + resid[(size_t)(r + 8) * C + cc];
                    outF[(size_t)(r + 8) * C + cc + 1] = f1.y + bias[cc + 1] + resid[(size_t)(r + 8) * C + cc + 1];
                    acch[mt][nt][0] = 0u; acch[mt][nt][1] = 0u;
                } else {
                    float* v = acc[mt][nt];
                    int e = n0 >> 9;
                    __half* dst = (e == 0) ? g_qh : ((e == 1) ? g_kh : g_vh);
                    int ch = (n0 & 511) + nl;
                    float b0f = g_bqr[n0 + nl], b1f = g_bqr[n0 + nl + 1];
                    *(__half2*)&dst[(size_t)r * C + ch] =
                        __floats2half2_rn(v[0] + b0f, v[1] + b1f);
                    *(__half2*)&dst[(size_t)(r + 8) * C + ch] =
                        __floats2half2_rn(v[2] + b0f, v[3] + b1f);
                    v[0] = v[1] = v[2] = v[3] = 0.f;
                }
            }
        }
    };

    load(0);
    load(1);

    for (int s = 0; s < S; s++) {
        if (s + 1 < S) { CPWAIT1(); } else { CPWAIT0(); }
        __syncthreads();
        load(s + 2);
        int st = s % 3;
        uint32_t a0[4][4], b0[8][2], a1[4][4], b1[8][2];
        ldfrag(st, 0,  a0, b0);
        ldfrag(st, 16, a1, b1);
        mma_all(a0, b0);
        ldfrag(st, 32, a0, b0);
        mma_all(a1, b1);
        ldfrag(st, 48, a1, b1);
        mma_all(a0, b0);
        mma_all(a1, b1);
        if ((s + 1) % KT == 0) epilogue(s / KT);
    }
}

// ---------------------------------------------------------------------------
// fp16 softmax (exp2 domain, deferred normalization): writes exp2(s-m) and
// stores 1/rowsum in g_rinv. 128 thr, uint4/thread, 2 barriers.
// ---------------------------------------------------------------------------
__global__ void softmax_h() {
    size_t row = blockIdx.x;
    uint4* p = (uint4*)(g_sh + row * HW);
    int tid = threadIdx.x, lane = tid & 31, warp = tid >> 5;
    uint4 raw = p[tid];
    __half2 h[4] = {*(__half2*)&raw.x, *(__half2*)&raw.y,
                    *(__half2*)&raw.z, *(__half2*)&raw.w};
    float2 f[4];
#pragma unroll
    for (int i = 0; i < 4; i++) f[i] = __half22float2(h[i]);

    float m = -1e30f;
#pragma unroll
    for (int i = 0; i < 4; i++) m = fmaxf(m, fmaxf(f[i].x, f[i].y));
#pragma unroll
    for (int o = 16; o; o >>= 1) m = fmaxf(m, __shfl_xor_sync(0xffffffffu, m, o));
    __shared__ float smax[4], ssum[4];
    if (lane == 0) smax[warp] = m;
    __syncthreads();
    m = fmaxf(fmaxf(smax[0], smax[1]), fmaxf(smax[2], smax[3]));

    float e[8];
    float s = 0.f;
#pragma unroll
    for (int i = 0; i < 4; i++) {
        e[2 * i]     = exp2f(f[i].x - m);
        e[2 * i + 1] = exp2f(f[i].y - m);
        s += e[2 * i] + e[2 * i + 1];
    }
#pragma unroll
    for (int o = 16; o; o >>= 1) s += __shfl_xor_sync(0xffffffffu, s, o);
    if (lane == 0) ssum[warp] = s;
    __syncthreads();
    float total = ssum[0] + ssum[1] + ssum[2] + ssum[3];
    if (tid == 0) g_rinv[row] = 1.0f / total;

    uint4 w;
    *(__half2*)&w.x = __floats2half2_rn(e[0], e[1]);
    *(__half2*)&w.y = __floats2half2_rn(e[2], e[3]);
    *(__half2*)&w.z = __floats2half2_rn(e[4], e[5]);
    *(__half2*)&w.w = __floats2half2_rn(e[6], e[7]);
    p[tid] = w;
}

// ---------------------------------------------------------------------------
extern "C" void kernel_launch(void* const* d_in, const int* in_sizes, int n_in,
                              void* d_out, int out_size) {
    (void)in_sizes; (void)n_in; (void)out_size;
    const float* inputs = (const float*)d_in[0];
    const float* gamma  = (const float*)d_in[1];
    const float* beta   = (const float*)d_in[2];
    const float* Wqkv   = (const float*)d_in[3];
    const float* bqkv   = (const float*)d_in[4];
    const float* Wout   = (const float*)d_in[5];
    const float* bout   = (const float*)d_in[6];
    float* out = (float*)d_out;

    const int smNT = 3 * (128 * 128 + 128 * 128);     // 98304
    const int smNN = 3 * (128 * 128 + 64 * 272);      // 101376
    cudaFuncSetAttribute(gemm_mma<0>, cudaFuncAttributeMaxDynamicSharedMemorySize, smNT);
    cudaFuncSetAttribute(gemm_mma<1>, cudaFuncAttributeMaxDynamicSharedMemorySize, smNT);
    cudaFuncSetAttribute(gemm_mma<2>, cudaFuncAttributeMaxDynamicSharedMemorySize, smNN);
    cudaFuncSetAttribute(gemm_mma<3>, cudaFuncAttributeMaxDynamicSharedMemorySize, smNN);

    prep_kernel<<<4608, 256>>>(inputs, gamma, beta, Wqkv, bqkv, Wout);

    gemm_mma<0><<<NPERS, 128, smNT>>>(nullptr, nullptr, nullptr);
    gemm_mma<1><<<NPERS, 128, smNT>>>(nullptr, nullptr, nullptr);
    softmax_h<<<BNUM * HW, 128>>>();
    gemm_mma<2><<<NPERS, 128, smNN>>>(nullptr, nullptr, nullptr);
    gemm_mma<3><<<NPERS, 128, smNN>>>(bout, inputs, out);
}